// round 9
// baseline (speedup 1.0000x reference)
#include <cuda_runtime.h>

#define HID  128
#define NIN  64
#define NOUT 64
#define NB   256
#define NS   4096

typedef unsigned long long u64;

// hs[b][s][jp] = {h[2jp], h[2jp+1]}. 512 MB.
__device__ u64 g_hs[NB][NS][HID / 2];
// chunk carry
__device__ u64 g_h[NB][HID / 2];

__device__ __forceinline__ u64 ffma2(u64 a, u64 b, u64 c) {
    u64 d;
    asm("fma.rn.f32x2 %0, %1, %2, %3;" : "=l"(d) : "l"(a), "l"(b), "l"(c));
    return d;
}
__device__ __forceinline__ u64 fadd2(u64 a, u64 b) {
    u64 d;
    asm("add.rn.f32x2 %0, %1, %2;" : "=l"(d) : "l"(a), "l"(b));
    return d;
}
__device__ __forceinline__ u64 pack2(float x, float y) {
    u64 d;
    asm("mov.b64 %0, {%1, %2};" : "=l"(d) : "f"(x), "f"(y));
    return d;
}
__device__ __forceinline__ float2 unpack2(u64 v) {
    float2 r;
    asm("mov.b64 {%0, %1}, %2;" : "=f"(r.x), "=f"(r.y) : "l"(v));
    return r;
}
__device__ __forceinline__ u64 shfl_xor64(u64 v, int m) {
    return __shfl_xor_sync(0xffffffffu, v, m);
}
// h skew: 2-u64 pad per 32-u64 block -> kq blocks at banks 0/4/8/12
#define KSK(k) ((k) + (((k) >> 5) << 1))

// ---------------------------------------------------------------------------
// Recurrence chunk [s0,s1), s0/s1 % 4 == 0. Fused x-projection.
// Grid: 128 CTAs x 256 thr. Two independent 128-thread row-groups per CTA
// (named barriers). Thread u: jq = u>>2 (j-quad, j0=4jq), kq = u&3 (k-quarter).
// Per thread: 2 j-pair accumulator chains over 32 k (Wh) + 16 i (Wx).
// Each LDS.128 (2 dup-k values) feeds 4 FFMA2 -> 24 LDS/thread/step (was 48).
// Weights register-resident: whd0/1[32] + wxd0/1[16] = 192 regs.
// kq partials reduced via shfl_xor(1),(2); one 128-thr barrier per step.
// ---------------------------------------------------------------------------
__global__ void __launch_bounds__(256, 1) rnn_rec_chunk(
    const float* __restrict__ x,  const float* __restrict__ Wh,
    const float* __restrict__ bh, const float* __restrict__ Wx,
    const float* __restrict__ bx, int s0, int s1)
{
    __shared__ __align__(16) u64 hbuf[2][2][136];   // [grp][buf][dup-h, skewed]
    __shared__ __align__(16) u64 xs[2][2][4][72];   // [grp][slot][st][dup-x, str18]

    const int tid = threadIdx.x;
    const int g   = tid >> 7;
    const int u   = tid & 127;
    const int jq  = u >> 2;       // 0..31 (j-quad)
    const int kq  = u & 3;        // k-quarter (lane bits -> shfl reduce)
    const int j0  = 4 * jq;
    const int k0  = kq * 32;      // Wh k-range
    const int i0  = kq * 16;      // Wx i-range
    const int b   = blockIdx.x * 2 + g;
    const int bar = g + 1;

    // Register-resident weight slices: one LDG.128 covers both j-pairs.
    u64 whd0[32], whd1[32];
#pragma unroll
    for (int m = 0; m < 32; m++) {
        ulonglong2 wv = *(const ulonglong2*)(Wh + (k0 + m) * HID + j0);
        whd0[m] = wv.x;           // {Wh[k][j0],   Wh[k][j0+1]}
        whd1[m] = wv.y;           // {Wh[k][j0+2], Wh[k][j0+3]}
    }
    u64 wxd0[16], wxd1[16];
#pragma unroll
    for (int m = 0; m < 16; m++) {
        ulonglong2 wv = *(const ulonglong2*)(Wx + (i0 + m) * HID + j0);
        wxd0[m] = wv.x;
        wxd1[m] = wv.y;
    }
    u64 bias0 = 0, bias1 = 0;
    if (kq == 0) {
        bias0 = pack2(bh[j0]     + bx[j0],     bh[j0 + 1] + bx[j0 + 1]);
        bias1 = pack2(bh[j0 + 2] + bx[j0 + 2], bh[j0 + 3] + bx[j0 + 3]);
    }

    // x stager mapping: step-in-block stq, 32 lanes cover 64 i as float2.
    const int stq = u >> 5;
    const int i2  = (u & 31) * 2;
    const int xsk = (i2 & 15) + 18 * (i2 >> 4);   // even -> 16B aligned
    const float* xrow = x + (long long)b * NS * NIN;

    const int B0 = s0 >> 2, B1 = s1 >> 2;

    // Prologue: init dup h, stage x block B0, prefetch B0+1.
    if (kq == 0) {
        float2 ha = make_float2(0.f, 0.f), hb2 = make_float2(0.f, 0.f);
        if (s0 != 0) {
            ha  = unpack2(g_h[b][2 * jq]);
            hb2 = unpack2(g_h[b][2 * jq + 1]);
        }
        ulonglong2 w2;
        w2.x = pack2(ha.x, ha.x);  w2.y = pack2(ha.y, ha.y);
        *(ulonglong2*)&hbuf[g][0][KSK(j0)] = w2;
        w2.x = pack2(hb2.x, hb2.x); w2.y = pack2(hb2.y, hb2.y);
        *(ulonglong2*)&hbuf[g][0][KSK(j0) + 2] = w2;
    }
    {
        float2 v = *(const float2*)(xrow + (long long)(4 * B0 + stq) * NIN + i2);
        ulonglong2 w2;
        w2.x = pack2(v.x, v.x);
        w2.y = pack2(v.y, v.y);
        *(ulonglong2*)&xs[g][B0 & 1][stq][xsk] = w2;
    }
    float2 xr = make_float2(0.f, 0.f);
    if (4 * (B0 + 1) < NS)
        xr = *(const float2*)(xrow + (long long)(4 * (B0 + 1) + stq) * NIN + i2);
    asm volatile("bar.sync %0, 128;" :: "r"(bar) : "memory");

    for (int bc = B0; bc < B1; bc++) {
        // Block head: stage x block bc+1, prefetch bc+2.
        if (4 * (bc + 1) < NS) {
            ulonglong2 w2;
            w2.x = pack2(xr.x, xr.x);
            w2.y = pack2(xr.y, xr.y);
            *(ulonglong2*)&xs[g][(bc + 1) & 1][stq][xsk] = w2;
        }
        if (4 * (bc + 2) < NS)
            xr = *(const float2*)(xrow + (long long)(4 * (bc + 2) + stq) * NIN + i2);

#pragma unroll
        for (int st = 0; st < 4; st++) {
            const int cur = st & 1, nxt = cur ^ 1;   // 4*bc even -> s&1 == st&1

            u64 a0 = bias0, b0a = 0;                  // jp0 chains
            u64 a1 = bias1, b1a = 0;                  // jp1 chains
            const u64* hb = &hbuf[g][cur][kq * 34];   // 32 contiguous u64
#pragma unroll
            for (int m = 0; m < 32; m += 2) {
                ulonglong2 hv = *(const ulonglong2*)(hb + m);
                a0  = ffma2(whd0[m],     hv.x, a0);
                a1  = ffma2(whd1[m],     hv.x, a1);
                b0a = ffma2(whd0[m + 1], hv.y, b0a);
                b1a = ffma2(whd1[m + 1], hv.y, b1a);
            }
            const u64* xb = &xs[g][bc & 1][st][kq * 18];  // 16 contiguous u64
#pragma unroll
            for (int m = 0; m < 16; m += 2) {
                ulonglong2 xv = *(const ulonglong2*)(xb + m);
                a0  = ffma2(wxd0[m],     xv.x, a0);
                a1  = ffma2(wxd1[m],     xv.x, a1);
                b0a = ffma2(wxd0[m + 1], xv.y, b0a);
                b1a = ffma2(wxd1[m + 1], xv.y, b1a);
            }
            u64 acc0 = fadd2(a0, b0a);
            u64 acc1 = fadd2(a1, b1a);
            acc0 = fadd2(acc0, shfl_xor64(acc0, 1));
            acc1 = fadd2(acc1, shfl_xor64(acc1, 1));
            acc0 = fadd2(acc0, shfl_xor64(acc0, 2));
            acc1 = fadd2(acc1, shfl_xor64(acc1, 2));

            if (kq == 0) {
                float2 t0 = unpack2(acc0), t1 = unpack2(acc1);
                t0.x = fmaxf(t0.x, 0.f);  t0.y = fmaxf(t0.y, 0.f);
                t1.x = fmaxf(t1.x, 0.f);  t1.y = fmaxf(t1.y, 0.f);
                ulonglong2 w2;
                w2.x = pack2(t0.x, t0.x); w2.y = pack2(t0.y, t0.y);
                *(ulonglong2*)&hbuf[g][nxt][KSK(j0)] = w2;
                w2.x = pack2(t1.x, t1.x); w2.y = pack2(t1.y, t1.y);
                *(ulonglong2*)&hbuf[g][nxt][KSK(j0) + 2] = w2;
                ulonglong2 hc;
                hc.x = pack2(t0.x, t0.y);
                hc.y = pack2(t1.x, t1.y);
                *(ulonglong2*)&g_hs[b][4 * bc + st][2 * jq] = hc;   // STG.128
                if (st == 3 && bc == B1 - 1)
                    *(ulonglong2*)&g_h[b][2 * jq] = hc;
            }
            asm volatile("bar.sync %0, 128;" :: "r"(bar) : "memory");
        }
    }
}

// ---------------------------------------------------------------------------
// Output: out[b][s][o] = hs[b][s]@Wy + by.  (unchanged, known-good)
// ---------------------------------------------------------------------------
__global__ void __launch_bounds__(256) rnn_output(
    const float* __restrict__ Wy, const float* __restrict__ by,
    float* __restrict__ out)
{
    __shared__ __align__(16) u64   hst[16][72];   // skewed, max index 69
    __shared__ __align__(16) float ot[16][64];

    const int t  = threadIdx.x;
    const int o  = t >> 2;
    const int jq = t & 3;
    const int b  = blockIdx.y;
    const int s0 = blockIdx.x * 16;

    u64 wyp[16];
#pragma unroll
    for (int m = 0; m < 16; m++) {
        int jpp = jq * 16 + m;
        wyp[m] = pack2(Wy[(2 * jpp) * NOUT + o], Wy[(2 * jpp + 1) * NOUT + o]);
    }
    float byv = by[o];

#pragma unroll
    for (int q = 0; q < 4; q++) {
        int idx = t + q * 256;
        int s = idx >> 6, jj = idx & 63;
        hst[s][jj + ((jj >> 4) << 1)] = g_hs[b][s0 + s][jj];
    }
    __syncthreads();

#pragma unroll 4
    for (int s = 0; s < 16; s++) {
        const u64* hrow = &hst[s][jq * 18];
        u64 accA = 0, accB = 0;
#pragma unroll
        for (int m = 0; m < 16; m += 2) {
            ulonglong2 hv = *(const ulonglong2*)(hrow + m);
            accA = ffma2(wyp[m],     hv.x, accA);
            accB = ffma2(wyp[m + 1], hv.y, accB);
        }
        u64 acc = fadd2(accA, accB);
        acc = fadd2(acc, shfl_xor64(acc, 1));
        acc = fadd2(acc, shfl_xor64(acc, 2));
        if (jq == 0) {
            float2 a = unpack2(acc);
            ot[s][o] = a.x + a.y + byv;
        }
    }
    __syncthreads();

#pragma unroll
    for (int q = 0; q < 4; q++) {
        int idx = t + q * 256;
        int s = idx >> 6, oo = idx & 63;
        out[((long long)b * NS + s0 + s) * NOUT + oo] = ot[s][oo];
    }
}

extern "C" void kernel_launch(void* const* d_in, const int* in_sizes, int n_in,
                              void* d_out, int out_size)
{
    const float* x  = (const float*)d_in[0];
    const float* Wh = (const float*)d_in[1];
    const float* bh = (const float*)d_in[2];
    const float* Wx = (const float*)d_in[3];
    const float* bx = (const float*)d_in[4];
    const float* Wy = (const float*)d_in[5];
    const float* by = (const float*)d_in[6];
    float* out = (float*)d_out;

    rnn_rec_chunk<<<NB / 2, 256>>>(x, Wh, bh, Wx, bx,    0, 1364);
    rnn_rec_chunk<<<NB / 2, 256>>>(x, Wh, bh, Wx, bx, 1364, 2732);
    rnn_rec_chunk<<<NB / 2, 256>>>(x, Wh, bh, Wx, bx, 2732, 4096);
    rnn_output<<<dim3(NS / 16, NB), 256>>>(Wy, by, out);
}

// round 10
// speedup vs baseline: 1.0692x; 1.0692x over previous
#include <cuda_runtime.h>

#define HID  128
#define NIN  64
#define NOUT 64
#define NB   256
#define NS   4096

typedef unsigned long long u64;

// hs[b][s][jp] = {h[2jp], h[2jp+1]}. 512 MB.
__device__ u64 g_hs[NB][NS][HID / 2];

__device__ __forceinline__ u64 ffma2(u64 a, u64 b, u64 c) {
    u64 d;
    asm("fma.rn.f32x2 %0, %1, %2, %3;" : "=l"(d) : "l"(a), "l"(b), "l"(c));
    return d;
}
__device__ __forceinline__ u64 fadd2(u64 a, u64 b) {
    u64 d;
    asm("add.rn.f32x2 %0, %1, %2;" : "=l"(d) : "l"(a), "l"(b));
    return d;
}
__device__ __forceinline__ u64 pack2(float x, float y) {
    u64 d;
    asm("mov.b64 %0, {%1, %2};" : "=l"(d) : "f"(x), "f"(y));
    return d;
}
__device__ __forceinline__ float2 unpack2(u64 v) {
    float2 r;
    asm("mov.b64 {%0, %1}, %2;" : "=f"(r.x), "=f"(r.y) : "l"(v));
    return r;
}
__device__ __forceinline__ u64 shfl_xor64(u64 v, int m) {
    return __shfl_xor_sync(0xffffffffu, v, m);
}
// skew: 2-u64 pad per 32-u64 block (keeps kh halves on distinct banks)
#define KSK(k) ((k) + (((k) >> 5) << 1))

// ---------------------------------------------------------------------------
// Recurrence chunk [s0,s1), s0/s1 % 4 == 0. Fused, software-pipelined x-proj.
// Grid: 128 CTAs x 256 thr (R8 shape). Two independent 128-thread row-groups
// per CTA (named barriers). Thread u: jp = u>>1, kh = u&1.
// whd[64] + wxd[32] register-resident (192 regs).
// Step s: h-MACs (64 FFMA2, acc init = bias+x-part(s) computed during s-1),
// fadd, shfl_xor(1) -- with x-part(s+1) MACs (32 FFMA2) issued inside the
// shfl window -- then split tail: kh0 lane dup-STS h to hbuf, kh1 lane
// compact-STG h to g_hs. One 128-thread named barrier per step.
// ---------------------------------------------------------------------------
__global__ void __launch_bounds__(256, 1) rnn_rec_chunk(
    const float* __restrict__ x,  const float* __restrict__ Wh,
    const float* __restrict__ bh, const float* __restrict__ Wx,
    const float* __restrict__ bx, int s0, int s1)
{
    __shared__ __align__(16) u64 hbuf[2][2][134];   // [grp][buf][dup-h, skewed]
    __shared__ __align__(16) u64 xs[2][2][4][66];   // [grp][slot][st][dup-x, skewed]

    const int tid = threadIdx.x;
    const int g   = tid >> 7;
    const int u   = tid & 127;
    const int jp  = u >> 1;       // 0..63
    const int kh  = u & 1;        // k-half (lane bit 0 -> shfl_xor(1) reduce)
    const int j0  = 2 * jp;
    const int b   = blockIdx.x * 2 + g;
    const int bar = g + 1;

    // Register-resident weight pair slices.
    u64 whd[64];
#pragma unroll
    for (int m = 0; m < 64; m++)
        whd[m] = *(const u64*)(Wh + (kh * 64 + m) * HID + j0);
    u64 wxd[32];
#pragma unroll
    for (int m = 0; m < 32; m++)
        wxd[m] = *(const u64*)(Wx + (kh * 32 + m) * HID + j0);
    u64 bias2 = 0;
    if (kh == 0)
        bias2 = pack2(bh[j0] + bx[j0], bh[j0 + 1] + bx[j0 + 1]);

    // x stager mapping: warp-uniform step stq, 32 lanes cover 64 i as float2.
    const int stq = u >> 5;            // step-in-block
    const int i2  = (u & 31) * 2;      // input col pair
    const int xsk = KSK(i2);
    const float* xrow = x + (long long)b * NS * NIN;

    const int B0 = s0 >> 2, B1 = s1 >> 2;

    // Prologue: init dup h (carry read from g_hs), stage x block B0,
    // prefetch block B0+1 into regs.
    if (kh == 0) {
        float2 h0 = make_float2(0.f, 0.f);
        if (s0 != 0) h0 = unpack2(g_hs[b][s0 - 1][jp]);
        ulonglong2 w2;
        w2.x = pack2(h0.x, h0.x);
        w2.y = pack2(h0.y, h0.y);
        *(ulonglong2*)&hbuf[g][0][KSK(j0)] = w2;
    }
    {
        float2 v = *(const float2*)(xrow + (long long)(4 * B0 + stq) * NIN + i2);
        ulonglong2 w2;
        w2.x = pack2(v.x, v.x);
        w2.y = pack2(v.y, v.y);
        *(ulonglong2*)&xs[g][B0 & 1][stq][xsk] = w2;
    }
    float2 xr = make_float2(0.f, 0.f);
    if (4 * (B0 + 1) < NS)
        xr = *(const float2*)(xrow + (long long)(4 * (B0 + 1) + stq) * NIN + i2);
    asm volatile("bar.sync %0, 128;" :: "r"(bar) : "memory");

    // Precompute x-part (+bias) for step s0.
    u64 xsvA, xsvB;
    {
        u64 a = bias2, bb = 0;
        const u64* xb = &xs[g][B0 & 1][0][kh * 34];
#pragma unroll
        for (int m = 0; m < 32; m += 2) {
            ulonglong2 xv = *(const ulonglong2*)(xb + m);
            a  = ffma2(wxd[m],     xv.x, a);
            bb = ffma2(wxd[m + 1], xv.y, bb);
        }
        xsvA = a;
        xsvB = bb;
    }

    for (int bc = B0; bc < B1; bc++) {
        // Block head: stage x block bc+1 (slot freed a block ago), prefetch bc+2.
        if (4 * (bc + 1) < NS) {
            ulonglong2 w2;
            w2.x = pack2(xr.x, xr.x);
            w2.y = pack2(xr.y, xr.y);
            *(ulonglong2*)&xs[g][(bc + 1) & 1][stq][xsk] = w2;
        }
        if (4 * (bc + 2) < NS)
            xr = *(const float2*)(xrow + (long long)(4 * (bc + 2) + stq) * NIN + i2);

#pragma unroll
        for (int st = 0; st < 4; st++) {
            const int cur = st & 1, nxt = cur ^ 1;   // 4*bc even -> s&1 == st&1
            const int nst   = (st + 1) & 3;          // next step's st
            const int nslot = (st < 3) ? (bc & 1) : ((bc + 1) & 1);

            // h-MACs for step s: acc init = bias + x-part(s).
            u64 accA = xsvA, accB = xsvB;
            const u64* hb = &hbuf[g][cur][kh * 68];
#pragma unroll
            for (int m = 0; m < 32; m += 2) {
                ulonglong2 hv = *(const ulonglong2*)(hb + m);
                accA = ffma2(whd[m],     hv.x, accA);
                accB = ffma2(whd[m + 1], hv.y, accB);
            }
#pragma unroll
            for (int m = 32; m < 64; m += 2) {
                ulonglong2 hv = *(const ulonglong2*)(hb + m + 2);   // skip pad
                accA = ffma2(whd[m],     hv.x, accA);
                accB = ffma2(whd[m + 1], hv.y, accB);
            }
            u64 acc = fadd2(accA, accB);
            u64 t   = shfl_xor64(acc, 1);            // k-half partner

            // x-part for step s+1: issued inside the shfl window (independent).
            {
                u64 a = bias2, bb = 0;
                const u64* xb = &xs[g][nslot][nst][kh * 34];
#pragma unroll
                for (int m = 0; m < 32; m += 2) {
                    ulonglong2 xv = *(const ulonglong2*)(xb + m);
                    a  = ffma2(wxd[m],     xv.x, a);
                    bb = ffma2(wxd[m + 1], xv.y, bb);
                }
                xsvA = a;
                xsvB = bb;
            }

            acc = fadd2(acc, t);                     // full sum in BOTH lanes
            float2 tv = unpack2(acc);
            tv.x = fmaxf(tv.x, 0.f);
            tv.y = fmaxf(tv.y, 0.f);
            if (kh == 0) {
                // dup h for next step's broadcast reads
                ulonglong2 w2;
                w2.x = pack2(tv.x, tv.x);
                w2.y = pack2(tv.y, tv.y);
                *(ulonglong2*)&hbuf[g][nxt][KSK(j0)] = w2;
            } else {
                // compact h to gmem (coalesced 128B per warp)
                g_hs[b][4 * bc + st][jp] = pack2(tv.x, tv.y);
            }
            asm volatile("bar.sync %0, 128;" :: "r"(bar) : "memory");
        }
    }
}

// ---------------------------------------------------------------------------
// Output: out[b][s][o] = hs[b][s]@Wy + by.  (unchanged, known-good)
// ---------------------------------------------------------------------------
__global__ void __launch_bounds__(256) rnn_output(
    const float* __restrict__ Wy, const float* __restrict__ by,
    float* __restrict__ out)
{
    __shared__ __align__(16) u64   hst[16][72];   // skewed, max index 69
    __shared__ __align__(16) float ot[16][64];

    const int t  = threadIdx.x;
    const int o  = t >> 2;
    const int jq = t & 3;
    const int b  = blockIdx.y;
    const int s0 = blockIdx.x * 16;

    u64 wyp[16];
#pragma unroll
    for (int m = 0; m < 16; m++) {
        int jpp = jq * 16 + m;
        wyp[m] = pack2(Wy[(2 * jpp) * NOUT + o], Wy[(2 * jpp + 1) * NOUT + o]);
    }
    float byv = by[o];

#pragma unroll
    for (int q = 0; q < 4; q++) {
        int idx = t + q * 256;
        int s = idx >> 6, jj = idx & 63;
        hst[s][jj + ((jj >> 4) << 1)] = g_hs[b][s0 + s][jj];
    }
    __syncthreads();

#pragma unroll 4
    for (int s = 0; s < 16; s++) {
        const u64* hrow = &hst[s][jq * 18];
        u64 accA = 0, accB = 0;
#pragma unroll
        for (int m = 0; m < 16; m += 2) {
            ulonglong2 hv = *(const ulonglong2*)(hrow + m);
            accA = ffma2(wyp[m],     hv.x, accA);
            accB = ffma2(wyp[m + 1], hv.y, accB);
        }
        u64 acc = fadd2(accA, accB);
        acc = fadd2(acc, shfl_xor64(acc, 1));
        acc = fadd2(acc, shfl_xor64(acc, 2));
        if (jq == 0) {
            float2 a = unpack2(acc);
            ot[s][o] = a.x + a.y + byv;
        }
    }
    __syncthreads();

#pragma unroll
    for (int q = 0; q < 4; q++) {
        int idx = t + q * 256;
        int s = idx >> 6, oo = idx & 63;
        out[((long long)b * NS + s0 + s) * NOUT + oo] = ot[s][oo];
    }
}

extern "C" void kernel_launch(void* const* d_in, const int* in_sizes, int n_in,
                              void* d_out, int out_size)
{
    const float* x  = (const float*)d_in[0];
    const float* Wh = (const float*)d_in[1];
    const float* bh = (const float*)d_in[2];
    const float* Wx = (const float*)d_in[3];
    const float* bx = (const float*)d_in[4];
    const float* Wy = (const float*)d_in[5];
    const float* by = (const float*)d_in[6];
    float* out = (float*)d_out;

    rnn_rec_chunk<<<NB / 2, 256>>>(x, Wh, bh, Wx, bx,    0, 1364);
    rnn_rec_chunk<<<NB / 2, 256>>>(x, Wh, bh, Wx, bx, 1364, 2732);
    rnn_rec_chunk<<<NB / 2, 256>>>(x, Wh, bh, Wx, bx, 2732, 4096);
    rnn_output<<<dim3(NS / 16, NB), 256>>>(Wy, by, out);
}

// round 11
// speedup vs baseline: 1.0762x; 1.0066x over previous
#include <cuda_runtime.h>

#define HID  128
#define NIN  64
#define NOUT 64
#define NB   256
#define NS   4096

typedef unsigned long long u64;

// hs[b][s][jp] = {h[2jp], h[2jp+1]}. 512 MB.
__device__ u64 g_hs[NB][NS][HID / 2];
// chunk carry
__device__ u64 g_h[NB][HID / 2];

__device__ __forceinline__ u64 ffma2(u64 a, u64 b, u64 c) {
    u64 d;
    asm("fma.rn.f32x2 %0, %1, %2, %3;" : "=l"(d) : "l"(a), "l"(b), "l"(c));
    return d;
}
__device__ __forceinline__ u64 fadd2(u64 a, u64 b) {
    u64 d;
    asm("add.rn.f32x2 %0, %1, %2;" : "=l"(d) : "l"(a), "l"(b));
    return d;
}
__device__ __forceinline__ u64 pack2(float x, float y) {
    u64 d;
    asm("mov.b64 %0, {%1, %2};" : "=l"(d) : "f"(x), "f"(y));
    return d;
}
__device__ __forceinline__ float2 unpack2(u64 v) {
    float2 r;
    asm("mov.b64 {%0, %1}, %2;" : "=f"(r.x), "=f"(r.y) : "l"(v));
    return r;
}
__device__ __forceinline__ u64 shfl_xor64(u64 v, int m) {
    return __shfl_xor_sync(0xffffffffu, v, m);
}
// skew: 2-u64 pad per 32-u64 block (keeps kh halves on distinct banks)
#define KSK(k) ((k) + (((k) >> 5) << 1))

// ---------------------------------------------------------------------------
// Recurrence chunk [s0,s1), s0/s1 % 4 == 0. Fused x-projection. (R8 base)
// Grid: 128 CTAs x 256 thr. Two independent 128-thread row-groups per CTA
// (named barriers). Thread u: jp = u>>1, kh = u&1.
// whd[64] + wxd[32] register-resident (192 regs).
// R11 changes vs R8:
//  - FOUR accumulator chains (depth 24 each, was 2 x 48) -> chain latency
//    halves and the FMA pipe gets 4-way ILP per thread.
//  - split tail: after shfl_xor(1) BOTH lanes hold the full sum; kh0 lane
//    writes the duplicated h to smem, kh1 lane writes compact h to g_hs.
// ---------------------------------------------------------------------------
__global__ void __launch_bounds__(256, 1) rnn_rec_chunk(
    const float* __restrict__ x,  const float* __restrict__ Wh,
    const float* __restrict__ bh, const float* __restrict__ Wx,
    const float* __restrict__ bx, int s0, int s1)
{
    __shared__ __align__(16) u64 hbuf[2][2][134];   // [grp][buf][dup-h, skewed]
    __shared__ __align__(16) u64 xs[2][2][4][66];   // [grp][slot][st][dup-x, skewed]

    const int tid = threadIdx.x;
    const int g   = tid >> 7;
    const int u   = tid & 127;
    const int jp  = u >> 1;       // 0..63
    const int kh  = u & 1;        // k-half (lane bit 0 -> shfl_xor(1) reduce)
    const int j0  = 2 * jp;
    const int b   = blockIdx.x * 2 + g;
    const int bar = g + 1;

    // Register-resident weight pair slices.
    u64 whd[64];
#pragma unroll
    for (int m = 0; m < 64; m++)
        whd[m] = *(const u64*)(Wh + (kh * 64 + m) * HID + j0);
    u64 wxd[32];
#pragma unroll
    for (int m = 0; m < 32; m++)
        wxd[m] = *(const u64*)(Wx + (kh * 32 + m) * HID + j0);
    u64 bias2 = 0;
    if (kh == 0)
        bias2 = pack2(bh[j0] + bx[j0], bh[j0 + 1] + bx[j0 + 1]);

    // x stager mapping: warp-uniform step stq, 32 lanes cover 64 i as float2.
    const int stq = u >> 5;            // step-in-block
    const int i2  = (u & 31) * 2;      // input col pair
    const int xsk = KSK(i2);
    const float* xrow = x + (long long)b * NS * NIN;

    const int B0 = s0 >> 2, B1 = s1 >> 2;

    // Prologue: init dup h, stage x block B0, prefetch block B0+1.
    if (kh == 0) {
        float2 h0 = make_float2(0.f, 0.f);
        if (s0 != 0) h0 = unpack2(g_h[b][jp]);
        ulonglong2 w2;
        w2.x = pack2(h0.x, h0.x);
        w2.y = pack2(h0.y, h0.y);
        *(ulonglong2*)&hbuf[g][0][KSK(j0)] = w2;
    }
    {
        float2 v = *(const float2*)(xrow + (long long)(4 * B0 + stq) * NIN + i2);
        ulonglong2 w2;
        w2.x = pack2(v.x, v.x);
        w2.y = pack2(v.y, v.y);
        *(ulonglong2*)&xs[g][B0 & 1][stq][xsk] = w2;
    }
    float2 xr = make_float2(0.f, 0.f);
    if (4 * (B0 + 1) < NS)
        xr = *(const float2*)(xrow + (long long)(4 * (B0 + 1) + stq) * NIN + i2);
    asm volatile("bar.sync %0, 128;" :: "r"(bar) : "memory");

    for (int bc = B0; bc < B1; bc++) {
        // Block head: stage x block bc+1 (slot freed a block ago), prefetch bc+2.
        if (4 * (bc + 1) < NS) {
            ulonglong2 w2;
            w2.x = pack2(xr.x, xr.x);
            w2.y = pack2(xr.y, xr.y);
            *(ulonglong2*)&xs[g][(bc + 1) & 1][stq][xsk] = w2;
        }
        if (4 * (bc + 2) < NS)
            xr = *(const float2*)(xrow + (long long)(4 * (bc + 2) + stq) * NIN + i2);

#pragma unroll
        for (int st = 0; st < 4; st++) {
            const int cur = st & 1, nxt = cur ^ 1;   // 4*bc even -> s&1 == st&1

            // FOUR accumulator chains (depth 16+8 each).
            u64 c0 = bias2, c1 = 0, c2 = 0, c3 = 0;
            const u64* hb = &hbuf[g][cur][kh * 68];
#pragma unroll
            for (int m = 0; m < 32; m += 4) {
                ulonglong2 hv0 = *(const ulonglong2*)(hb + m);
                ulonglong2 hv1 = *(const ulonglong2*)(hb + m + 2);
                c0 = ffma2(whd[m],     hv0.x, c0);
                c1 = ffma2(whd[m + 1], hv0.y, c1);
                c2 = ffma2(whd[m + 2], hv1.x, c2);
                c3 = ffma2(whd[m + 3], hv1.y, c3);
            }
#pragma unroll
            for (int m = 32; m < 64; m += 4) {
                ulonglong2 hv0 = *(const ulonglong2*)(hb + m + 2);   // skip pad
                ulonglong2 hv1 = *(const ulonglong2*)(hb + m + 4);
                c0 = ffma2(whd[m],     hv0.x, c0);
                c1 = ffma2(whd[m + 1], hv0.y, c1);
                c2 = ffma2(whd[m + 2], hv1.x, c2);
                c3 = ffma2(whd[m + 3], hv1.y, c3);
            }
            const u64* xb = &xs[g][bc & 1][st][kh * 34];
#pragma unroll
            for (int m = 0; m < 32; m += 4) {
                ulonglong2 xv0 = *(const ulonglong2*)(xb + m);
                ulonglong2 xv1 = *(const ulonglong2*)(xb + m + 2);
                c0 = ffma2(wxd[m],     xv0.x, c0);
                c1 = ffma2(wxd[m + 1], xv0.y, c1);
                c2 = ffma2(wxd[m + 2], xv1.x, c2);
                c3 = ffma2(wxd[m + 3], xv1.y, c3);
            }
            u64 acc = fadd2(fadd2(c0, c1), fadd2(c2, c3));
            acc = fadd2(acc, shfl_xor64(acc, 1));    // full sum in BOTH lanes

            float2 tv = unpack2(acc);
            tv.x = fmaxf(tv.x, 0.f);
            tv.y = fmaxf(tv.y, 0.f);
            if (kh == 0) {
                // dup h for next step's broadcast reads
                ulonglong2 w2;
                w2.x = pack2(tv.x, tv.x);
                w2.y = pack2(tv.y, tv.y);
                *(ulonglong2*)&hbuf[g][nxt][KSK(j0)] = w2;
            } else {
                // compact h to gmem (coalesced per warp)
                u64 h2 = pack2(tv.x, tv.y);
                g_hs[b][4 * bc + st][jp] = h2;
                if (st == 3 && bc == B1 - 1) g_h[b][jp] = h2;
            }
            asm volatile("bar.sync %0, 128;" :: "r"(bar) : "memory");
        }
    }
}

// ---------------------------------------------------------------------------
// Output: out[b][s][o] = hs[b][s]@Wy + by.  (unchanged, known-good)
// ---------------------------------------------------------------------------
__global__ void __launch_bounds__(256) rnn_output(
    const float* __restrict__ Wy, const float* __restrict__ by,
    float* __restrict__ out)
{
    __shared__ __align__(16) u64   hst[16][72];   // skewed, max index 69
    __shared__ __align__(16) float ot[16][64];

    const int t  = threadIdx.x;
    const int o  = t >> 2;
    const int jq = t & 3;
    const int b  = blockIdx.y;
    const int s0 = blockIdx.x * 16;

    u64 wyp[16];
#pragma unroll
    for (int m = 0; m < 16; m++) {
        int jpp = jq * 16 + m;
        wyp[m] = pack2(Wy[(2 * jpp) * NOUT + o], Wy[(2 * jpp + 1) * NOUT + o]);
    }
    float byv = by[o];

#pragma unroll
    for (int q = 0; q < 4; q++) {
        int idx = t + q * 256;
        int s = idx >> 6, jj = idx & 63;
        hst[s][jj + ((jj >> 4) << 1)] = g_hs[b][s0 + s][jj];
    }
    __syncthreads();

#pragma unroll 4
    for (int s = 0; s < 16; s++) {
        const u64* hrow = &hst[s][jq * 18];
        u64 accA = 0, accB = 0;
#pragma unroll
        for (int m = 0; m < 16; m += 2) {
            ulonglong2 hv = *(const ulonglong2*)(hrow + m);
            accA = ffma2(wyp[m],     hv.x, accA);
            accB = ffma2(wyp[m + 1], hv.y, accB);
        }
        u64 acc = fadd2(accA, accB);
        acc = fadd2(acc, shfl_xor64(acc, 1));
        acc = fadd2(acc, shfl_xor64(acc, 2));
        if (jq == 0) {
            float2 a = unpack2(acc);
            ot[s][o] = a.x + a.y + byv;
        }
    }
    __syncthreads();

#pragma unroll
    for (int q = 0; q < 4; q++) {
        int idx = t + q * 256;
        int s = idx >> 6, oo = idx & 63;
        out[((long long)b * NS + s0 + s) * NOUT + oo] = ot[s][oo];
    }
}

extern "C" void kernel_launch(void* const* d_in, const int* in_sizes, int n_in,
                              void* d_out, int out_size)
{
    const float* x  = (const float*)d_in[0];
    const float* Wh = (const float*)d_in[1];
    const float* bh = (const float*)d_in[2];
    const float* Wx = (const float*)d_in[3];
    const float* bx = (const float*)d_in[4];
    const float* Wy = (const float*)d_in[5];
    const float* by = (const float*)d_in[6];
    float* out = (float*)d_out;

    rnn_rec_chunk<<<NB / 2, 256>>>(x, Wh, bh, Wx, bx,    0, 1364);
    rnn_rec_chunk<<<NB / 2, 256>>>(x, Wh, bh, Wx, bx, 1364, 2732);
    rnn_rec_chunk<<<NB / 2, 256>>>(x, Wh, bh, Wx, bx, 2732, 4096);
    rnn_output<<<dim3(NS / 16, NB), 256>>>(Wy, by, out);
}